// round 13
// baseline (speedup 1.0000x reference)
#include <cuda_runtime.h>
#include <cuda_bf16.h>
#include <cstdint>
#include <math.h>

// ---------------- problem dims ----------------
#define NB    8192
#define HD    128
#define H1    18
#define H2    8
#define FLAT  2048
#define FEAT  144
#define G3H   384

// ---------------- scratch ----------------
__device__ float g_conv1[NB * 16 * H1 * H1];   // NHWC: [n][y][x][c16]
__device__ float g_flat [NB * FLAT];           // [n][px64][oc32]
__device__ float g_fvwp [HD * FLAT];           // permuted fc_vis_w
__device__ float g_feat [NB * FEAT];
__device__ float g_gi   [NB * G3H];
__device__ float g_gh   [NB * G3H];
__device__ float g_Q    [NB * HD];
__device__ float g_K    [NB * HD];
__device__ float g_V    [NB * HD];
__device__ float g_ctx  [NB * HD];
__device__ float g_swarm[NB * HD];
__device__ __nv_bfloat16 g_Kb[NB * HD];
__device__ __nv_bfloat16 g_Vb[NB * HD];
__device__ float g_Opart[2 * NB * HD];
__device__ float g_lpart[2 * NB];
__device__ int   g_isI32;

// ---------------- packed fp32x2 FMA (Blackwell base ISA, exact fp32) ----------------
typedef unsigned long long ull;
#define FMA2(d, a, b) \
    asm("fma.rn.f32x2 %0, %1, %2, %0;" : "+l"(d) : "l"(a), "l"(b))
__device__ __forceinline__ ull pk2(float x, float y) {
    ull r; asm("mov.b64 %0, {%1, %2};" : "=l"(r) : "f"(x), "f"(y)); return r;
}
__device__ __forceinline__ float2 upk2(ull v) {
    float2 f; asm("mov.b64 {%0, %1}, %2;" : "=f"(f.x), "=f"(f.y) : "l"(v)); return f;
}

// ---------------- mma/ldmatrix helpers (base ISA, legal on sm_103) ----------------
__device__ __forceinline__ uint32_t smem_u32(const void* p) {
    uint32_t a;
    asm("{ .reg .u64 t; cvta.to.shared.u64 t, %1; cvt.u32.u64 %0, t; }" : "=r"(a) : "l"(p));
    return a;
}
#define LDSM_X4(r0, r1, r2, r3, a) \
    asm volatile("ldmatrix.sync.aligned.m8n8.x4.shared.b16 {%0,%1,%2,%3}, [%4];" \
        : "=r"(r0), "=r"(r1), "=r"(r2), "=r"(r3) : "r"(a))
#define LDSM_X4T(r0, r1, r2, r3, a) \
    asm volatile("ldmatrix.sync.aligned.m8n8.x4.trans.shared.b16 {%0,%1,%2,%3}, [%4];" \
        : "=r"(r0), "=r"(r1), "=r"(r2), "=r"(r3) : "r"(a))
#define MMA_BF16(d, a, b0, b1) \
    asm volatile("mma.sync.aligned.m16n8k16.row.col.f32.bf16.bf16.f32 " \
        "{%0,%1,%2,%3}, {%4,%5,%6,%7}, {%8,%9}, {%0,%1,%2,%3};" \
        : "+f"((d)[0]), "+f"((d)[1]), "+f"((d)[2]), "+f"((d)[3]) \
        : "r"((a)[0]), "r"((a)[1]), "r"((a)[2]), "r"((a)[3]), "r"(b0), "r"(b1))

__device__ __forceinline__ uint32_t packbf(float x, float y) {
    __nv_bfloat162 h = __floats2bfloat162_rn(x, y);
    return *(uint32_t*)&h;
}

// ---------------- class_ids dtype detection ----------------
__global__ void k_flag_init() { g_isI32 = 0; }
__global__ void k_flag_detect(const int* __restrict__ p) {
    int i = blockIdx.x * blockDim.x + threadIdx.x;
    if (i < 4096 && p[2 * i + 1] != 0) g_isI32 = 1;
}

// ---------------- conv1: 3 px/thread, 16 oc, f32x2; NHWC output ----------------
__global__ void k_conv1(const float* __restrict__ img, const float* __restrict__ w,
                        const float* __restrict__ b, float* __restrict__ out) {
    __shared__ float ws[75 * 16];   // [k][oc]
    __shared__ float bs[16];
    for (int i = threadIdx.x; i < 1200; i += 256) {
        int oc = i / 75, k = i % 75;
        ws[k * 16 + oc] = w[i];
    }
    if (threadIdx.x < 16) bs[threadIdx.x] = b[threadIdx.x];
    __syncthreads();

    int idx = blockIdx.x * 256 + threadIdx.x;   // 8192*18*6 items
    int g  = idx % 6;
    int oy = (idx / 6) % H1;
    int n  = idx / (6 * H1);
    int ox0 = g * 3;
    const float* ip = img + (size_t)n * 4800;

    ull acc[3][8];                  // 3 px x 8 oc-pairs
    #pragma unroll
    for (int p = 0; p < 3; p++)
        #pragma unroll
        for (int q = 0; q < 8; q++) acc[p][q] = pk2(bs[2 * q], bs[2 * q + 1]);

    #pragma unroll
    for (int ic = 0; ic < 3; ic++) {
        #pragma unroll
        for (int ky = 0; ky < 5; ky++) {
            const float* row = ip + ic * 1600 + (2 * oy + ky) * 40 + ox0 * 2;
            float rv[9];
            #pragma unroll
            for (int x = 0; x < 9; x++) rv[x] = row[x];
            #pragma unroll
            for (int kx = 0; kx < 5; kx++) {
                const ulonglong2* wp = (const ulonglong2*)&ws[((ic * 5 + ky) * 5 + kx) * 16];
                ulonglong2 w0 = wp[0], w1 = wp[1], w2 = wp[2], w3 = wp[3];
                #pragma unroll
                for (int p = 0; p < 3; p++) {
                    ull vv = pk2(rv[2 * p + kx], rv[2 * p + kx]);
                    FMA2(acc[p][0], vv, w0.x); FMA2(acc[p][1], vv, w0.y);
                    FMA2(acc[p][2], vv, w1.x); FMA2(acc[p][3], vv, w1.y);
                    FMA2(acc[p][4], vv, w2.x); FMA2(acc[p][5], vv, w2.y);
                    FMA2(acc[p][6], vv, w3.x); FMA2(acc[p][7], vv, w3.y);
                }
            }
        }
    }
    // NHWC store: out[n][oy][ox0+p][c16], oc pairs contiguous
    float* op = out + (size_t)n * (H1 * H1 * 16) + (oy * H1 + ox0) * 16;
    #pragma unroll
    for (int p = 0; p < 3; p++) {
        ull* dst = (ull*)(op + p * 16);
        #pragma unroll
        for (int q = 0; q < 8; q++) {
            float2 v = upk2(acc[p][q]);
            dst[q] = pk2(fmaxf(v.x, 0.f), fmaxf(v.y, 0.f));
        }
    }
}

// ---------------- conv2: NHWC input, 2 px/thread, 32 oc, f32x2 ----------------
// smem weights [tap9][ic16][oc32]; output [n][px64][oc32]
#define C2STEP(comp, off) { \
    ull v0 = pk2(a.comp, a.comp), v1 = pk2(c.comp, c.comp); \
    const ulonglong2* wp = (const ulonglong2*)&wk[(icg * 4 + off) * 32]; \
    _Pragma("unroll") \
    for (int q = 0; q < 8; q++) { \
        ulonglong2 wv = wp[q]; \
        FMA2(acc[0][2 * q], v0, wv.x); FMA2(acc[0][2 * q + 1], v0, wv.y); \
        FMA2(acc[1][2 * q], v1, wv.x); FMA2(acc[1][2 * q + 1], v1, wv.y); \
    } }
__global__ void __launch_bounds__(256, 2)
k_conv2(const float* __restrict__ in, const float* __restrict__ w,
        const float* __restrict__ b, float* __restrict__ out) {
    __shared__ float ws[9 * 512];   // [kk][ic][oc]
    __shared__ float bs[32];
    for (int i = threadIdx.x; i < 4608; i += 256) {
        int oc = i / 144, r = i % 144, ic = r / 9, kk = r % 9;
        ws[kk * 512 + ic * 32 + oc] = w[i];
    }
    if (threadIdx.x < 32) bs[threadIdx.x] = b[threadIdx.x];
    __syncthreads();

    int idx = blockIdx.x * 256 + threadIdx.x;   // NB*8*4
    int g  = idx & 3;
    int oy = (idx >> 2) & 7;
    int n  = idx >> 5;
    int ox0 = g * 2;
    const float* ip = in + (size_t)n * (H1 * H1 * 16);

    ull acc[2][16];
    #pragma unroll
    for (int p = 0; p < 2; p++)
        #pragma unroll
        for (int q = 0; q < 16; q++) acc[p][q] = pk2(bs[2 * q], bs[2 * q + 1]);

    #pragma unroll
    for (int ky = 0; ky < 3; ky++) {
        #pragma unroll
        for (int kx = 0; kx < 3; kx++) {
            const float* wk = ws + (ky * 3 + kx) * 512;
            const float4* i0 = (const float4*)(ip + ((2 * oy + ky) * H1 + 2 * ox0 + kx) * 16);
            const float4* i1 = i0 + 8;     // next output pixel = +2 input px = +32 floats
            #pragma unroll
            for (int icg = 0; icg < 4; icg++) {
                float4 a = i0[icg];
                float4 c = i1[icg];
                C2STEP(x, 0)
                C2STEP(y, 1)
                C2STEP(z, 2)
                C2STEP(w, 3)
            }
        }
    }
    // store [px][oc]: oc pairs contiguous
    float* op = out + (size_t)n * FLAT + (oy * H2 + ox0) * 32;
    #pragma unroll
    for (int p = 0; p < 2; p++) {
        ull* dst = (ull*)(op + p * 32);
        #pragma unroll
        for (int q = 0; q < 16; q++) {
            float2 v = upk2(acc[p][q]);
            dst[q] = pk2(fmaxf(v.x, 0.f), fmaxf(v.y, 0.f));
        }
    }
}

// ---------------- fc_vis weight permute: dst[h][p*32+oc] = src[h][oc*64+p] ----------------
__global__ void k_permw(const float* __restrict__ src, float* __restrict__ dst) {
    int idx = blockIdx.x * 256 + threadIdx.x;   // 128*2048
    int h = idx >> 11, j = idx & 2047;
    int p = j >> 5, oc = j & 31;
    dst[idx] = src[h * FLAT + oc * 64 + p];
}

// ------- fp32 SGEMM: C[M,N] = act(A[M,K] @ B[N,K]^T + bias), 128x64 tile, BK=16, f32x2 -------
__global__ void __launch_bounds__(256, 2)
k_gemm128(const float* __restrict__ A, int lda,
          const float* __restrict__ B, int ldb,
          const float* __restrict__ bias,
          float* __restrict__ C, int ldc,
          int K, int act) {
    __shared__ float As[16][132];
    __shared__ float Bs[16][68];
    int m0 = blockIdx.y * 128, n0 = blockIdx.x * 64;
    int tid = threadIdx.x;
    int ra = tid >> 1, ka = (tid & 1) * 8;
    int rb = tid >> 2, kb = (tid & 3) * 4;
    int tr = tid >> 4, tc = tid & 15;

    ull acc[8][2];
    #pragma unroll
    for (int i = 0; i < 8; i++) { acc[i][0] = pk2(0.f, 0.f); acc[i][1] = pk2(0.f, 0.f); }

    const float* Ap = A + (size_t)(m0 + ra) * lda + ka;
    const float* Bp = B + (size_t)(n0 + rb) * ldb + kb;

    for (int k0 = 0; k0 < K; k0 += 16) {
        float4 a0 = *(const float4*)(Ap + k0);
        float4 a1 = *(const float4*)(Ap + k0 + 4);
        float4 bv = *(const float4*)(Bp + k0);
        As[ka + 0][ra] = a0.x; As[ka + 1][ra] = a0.y; As[ka + 2][ra] = a0.z; As[ka + 3][ra] = a0.w;
        As[ka + 4][ra] = a1.x; As[ka + 5][ra] = a1.y; As[ka + 6][ra] = a1.z; As[ka + 7][ra] = a1.w;
        Bs[kb + 0][rb] = bv.x; Bs[kb + 1][rb] = bv.y; Bs[kb + 2][rb] = bv.z; Bs[kb + 3][rb] = bv.w;
        __syncthreads();
        #pragma unroll
        for (int k = 0; k < 16; k++) {
            float4 x0 = *(const float4*)&As[k][tr * 4];
            float4 x1 = *(const float4*)&As[k][tr * 4 + 64];
            ulonglong2 yv = *(const ulonglong2*)&Bs[k][tc * 4];
            ull v;
            v = pk2(x0.x, x0.x); FMA2(acc[0][0], v, yv.x); FMA2(acc[0][1], v, yv.y);
            v = pk2(x0.y, x0.y); FMA2(acc[1][0], v, yv.x); FMA2(acc[1][1], v, yv.y);
            v = pk2(x0.z, x0.z); FMA2(acc[2][0], v, yv.x); FMA2(acc[2][1], v, yv.y);
            v = pk2(x0.w, x0.w); FMA2(acc[3][0], v, yv.x); FMA2(acc[3][1], v, yv.y);
            v = pk2(x1.x, x1.x); FMA2(acc[4][0], v, yv.x); FMA2(acc[4][1], v, yv.y);
            v = pk2(x1.y, x1.y); FMA2(acc[5][0], v, yv.x); FMA2(acc[5][1], v, yv.y);
            v = pk2(x1.z, x1.z); FMA2(acc[6][0], v, yv.x); FMA2(acc[6][1], v, yv.y);
            v = pk2(x1.w, x1.w); FMA2(acc[7][0], v, yv.x); FMA2(acc[7][1], v, yv.y);
        }
        __syncthreads();
    }

    float bb[4];
    #pragma unroll
    for (int j = 0; j < 4; j++) bb[j] = bias[n0 + tc * 4 + j];
    #pragma unroll
    for (int i = 0; i < 8; i++) {
        int row = m0 + tr * 4 + (i & 3) + (i >> 2) * 64;
        float2 p0 = upk2(acc[i][0]);
        float2 p1 = upk2(acc[i][1]);
        float4 o;
        o.x = p0.x + bb[0]; o.y = p0.y + bb[1];
        o.z = p1.x + bb[2]; o.w = p1.y + bb[3];
        if (act == 1) {
            o.x = fmaxf(o.x, 0.f); o.y = fmaxf(o.y, 0.f);
            o.z = fmaxf(o.z, 0.f); o.w = fmaxf(o.w, 0.f);
        }
        *(float4*)(C + (size_t)row * ldc + n0 + tc * 4) = o;
    }
}

// ---------------- embedding ----------------
__global__ void k_embed(const int* __restrict__ cls, const float* __restrict__ table,
                        float* __restrict__ feat) {
    int idx = blockIdx.x * 256 + threadIdx.x;
    if (idx >= NB * 16) return;
    int i = idx >> 4, j = idx & 15;
    int id = g_isI32 ? cls[i] : cls[2 * i];
    feat[i * FEAT + 128 + j] = table[id * 16 + j];
}

// ---------------- GRU ----------------
__global__ void k_gru(const float* __restrict__ gi, const float* __restrict__ gh,
                      const float* __restrict__ h, float* __restrict__ nh) {
    int idx = blockIdx.x * 256 + threadIdx.x;
    if (idx >= NB * HD) return;
    int i = idx >> 7, j = idx & 127;
    const float* a = gi + i * G3H;
    const float* c = gh + i * G3H;
    float r = 1.f / (1.f + __expf(-(a[j] + c[j])));
    float z = 1.f / (1.f + __expf(-(a[128 + j] + c[128 + j])));
    float n = tanhf(a[256 + j] + r * c[256 + j]);
    nh[idx] = (1.f - z) * n + z * h[idx];
}

// ---------------- fp32 -> bf16 convert ----------------
__global__ void k_cvtbf(const float* __restrict__ X, __nv_bfloat16* __restrict__ Y) {
    int i = blockIdx.x * 256 + threadIdx.x;
    float2 v = ((const float2*)X)[i];
    ((__nv_bfloat162*)Y)[i] = __floats2bfloat162_rn(v.x, v.y);
}

// ============ mma.sync bf16 flash attention (split-KV over 2 halves) ============
__global__ void __launch_bounds__(256, 1)
k_attn_mma(const float* __restrict__ Qf, const __nv_bfloat16* __restrict__ Kb,
           const __nv_bfloat16* __restrict__ Vb, const int* __restrict__ adj,
           float* __restrict__ Opart, float* __restrict__ lpart) {
    extern __shared__ char smem[];
    char* Ks = smem;            // 128 rows x 256B (swizzled)
    char* Vs = smem + 32768;
    uint32_t KsA = smem_u32(Ks);
    uint32_t VsA = smem_u32(Vs);

    int tid  = threadIdx.x;
    int wid  = tid >> 5;
    int lane = tid & 31;
    int m    = lane >> 3;
    int row0 = (blockIdx.x & 63) * 128;
    int half = blockIdx.x >> 6;
    int cst  = half * 4096;
    const float scale = 0.08838834764831845f;

    #pragma unroll
    for (int it = 0; it < 8; it++) {
        int id = tid + it * 256;
        int r = id >> 4, u = id & 15;
        const float4* qp = (const float4*)(Qf + (size_t)(row0 + r) * 128 + u * 8);
        float4 v0 = qp[0], v1 = qp[1];
        uint32_t pk[4] = { packbf(v0.x, v0.y), packbf(v0.z, v0.w),
                           packbf(v1.x, v1.y), packbf(v1.z, v1.w) };
        *(int4*)(Ks + r * 256 + ((u ^ (r & 7)) * 16)) = *(int4*)pk;
    }
    __syncthreads();

    uint32_t qf[8][4];
    #pragma unroll
    for (int kk = 0; kk < 8; kk++) {
        int r = wid * 16 + (m & 1) * 8 + (lane & 7);
        int u = kk * 2 + (m >> 1);
        uint32_t a = KsA + r * 256 + ((u ^ (r & 7)) * 16);
        LDSM_X4(qf[kk][0], qf[kk][1], qf[kk][2], qf[kk][3], a);
    }
    __syncthreads();

    float oacc[16][4];
    #pragma unroll
    for (int j = 0; j < 16; j++)
        #pragma unroll
        for (int i = 0; i < 4; i++) oacc[j][i] = 0.f;
    float lsum0 = 0.f, lsum1 = 0.f;

    int grow0 = row0 + wid * 16 + (lane >> 2);
    const int* adjr0 = adj + (size_t)grow0 * NB;
    const int* adjr1 = adjr0 + (size_t)8 * NB;

    for (int t = 0; t < 32; t++) {
        int c0 = cst + t * 128;
        #pragma unroll
        for (int it = 0; it < 8; it++) {
            int id = tid + it * 256;
            int r = id >> 4, u = id & 15;
            int4 kv = *(const int4*)(Kb + (size_t)(c0 + r) * 128 + u * 8);
            int4 vv = *(const int4*)(Vb + (size_t)(c0 + r) * 128 + u * 8);
            int off = r * 256 + ((u ^ (r & 7)) * 16);
            *(int4*)(Ks + off) = kv;
            *(int4*)(Vs + off) = vv;
        }
        __syncthreads();

        float sacc[16][4];
        #pragma unroll
        for (int j = 0; j < 16; j++)
            #pragma unroll
            for (int i = 0; i < 4; i++) sacc[j][i] = 0.f;

        #pragma unroll
        for (int kk = 0; kk < 8; kk++) {
            #pragma unroll
            for (int jp = 0; jp < 8; jp++) {
                int nr = jp * 16 + (m >> 1) * 8 + (lane & 7);
                int u  = kk * 2 + (m & 1);
                uint32_t a = KsA + nr * 256 + ((u ^ (nr & 7)) * 16);
                uint32_t b0, b1, b2, b3;
                LDSM_X4(b0, b1, b2, b3, a);
                MMA_BF16(sacc[2 * jp],     qf[kk], b0, b1);
                MMA_BF16(sacc[2 * jp + 1], qf[kk], b2, b3);
            }
        }

        uint32_t pf[8][4];
        int cb = c0 + (lane & 3) * 2;
        #pragma unroll
        for (int s = 0; s < 8; s++) {
            int ca = cb + s * 16;
            int cbb = ca + 8;
            int2 m00 = *(const int2*)(adjr0 + ca);
            int2 m01 = *(const int2*)(adjr1 + ca);
            int2 m10 = *(const int2*)(adjr0 + cbb);
            int2 m11 = *(const int2*)(adjr1 + cbb);
            float p00 = m00.x ? __expf(sacc[2 * s][0] * scale) : 0.f;
            float p01 = m00.y ? __expf(sacc[2 * s][1] * scale) : 0.f;
            float p02 = m01.x ? __expf(sacc[2 * s][2] * scale) : 0.f;
            float p03 = m01.y ? __expf(sacc[2 * s][3] * scale) : 0.f;
            float p10 = m10.x ? __expf(sacc[2 * s + 1][0] * scale) : 0.f;
            float p11 = m10.y ? __expf(sacc[2 * s + 1][1] * scale) : 0.f;
            float p12 = m11.x ? __expf(sacc[2 * s + 1][2] * scale) : 0.f;
            float p13 = m11.y ? __expf(sacc[2 * s + 1][3] * scale) : 0.f;
            lsum0 += (p00 + p01) + (p10 + p11);
            lsum1 += (p02 + p03) + (p12 + p13);
            pf[s][0] = packbf(p00, p01);
            pf[s][1] = packbf(p02, p03);
            pf[s][2] = packbf(p10, p11);
            pf[s][3] = packbf(p12, p13);
        }

        #pragma unroll
        for (int sp = 0; sp < 4; sp++) {
            #pragma unroll
            for (int jj = 0; jj < 16; jj++) {
                int cr = sp * 32 + m * 8 + (lane & 7);
                uint32_t a = VsA + cr * 256 + ((jj ^ (cr & 7)) * 16);
                uint32_t b0, b1, b2, b3;
                LDSM_X4T(b0, b1, b2, b3, a);
                MMA_BF16(oacc[jj], pf[2 * sp],     b0, b1);
                MMA_BF16(oacc[jj], pf[2 * sp + 1], b2, b3);
            }
        }
        __syncthreads();
    }

    lsum0 += __shfl_xor_sync(0xffffffffu, lsum0, 1);
    lsum0 += __shfl_xor_sync(0xffffffffu, lsum0, 2);
    lsum1 += __shfl_xor_sync(0xffffffffu, lsum1, 1);
    lsum1 += __shfl_xor_sync(0xffffffffu, lsum1, 2);
    if ((lane & 3) == 0) {
        lpart[half * NB + grow0]     = lsum0;
        lpart[half * NB + grow0 + 8] = lsum1;
    }
    float* o0 = Opart + ((size_t)half * NB + grow0) * 128 + (lane & 3) * 2;
    float* o1 = o0 + (size_t)8 * 128;
    #pragma unroll
    for (int jj = 0; jj < 16; jj++) {
        *(float2*)(o0 + jj * 8) = make_float2(oacc[jj][0], oacc[jj][1]);
        *(float2*)(o1 + jj * 8) = make_float2(oacc[jj][2], oacc[jj][3]);
    }
}

// ---------------- merge split-KV halves ----------------
__global__ void k_merge(const float* __restrict__ O, const float* __restrict__ l,
                        float* __restrict__ ctx) {
    int idx = blockIdx.x * 256 + threadIdx.x;
    int r = idx >> 7;
    float denom = l[r] + l[NB + r];
    ctx[idx] = (O[idx] + O[NB * HD + idx]) / denom;
}

// ---------------- final head ----------------
__global__ void k_fcq(const float* __restrict__ nh, const float* __restrict__ sw,
                      const float* __restrict__ W, const float* __restrict__ b,
                      float* __restrict__ q) {
    int idx = blockIdx.x * 256 + threadIdx.x;
    if (idx >= NB * 5) return;
    int i = idx / 5, a = idx % 5;
    const float* w = W + a * 256;
    const float* hr = nh + i * 128;
    const float* sr = sw + i * 128;
    float s = b[a];
    #pragma unroll 8
    for (int k = 0; k < 128; k++) s += hr[k] * w[k];
    #pragma unroll 8
    for (int k = 0; k < 128; k++) s += sr[k] * w[128 + k];
    q[idx] = s;
}

// ---------------- launch ----------------
extern "C" void kernel_launch(void* const* d_in, const int* in_sizes, int n_in,
                              void* d_out, int out_size) {
    const float* img = (const float*)d_in[0];
    const int*   adj = (const int*)  d_in[1];
    const int*   cls = (const int*)  d_in[2];
    const float* h0  = (const float*)d_in[3];
    const float* c1w = (const float*)d_in[4];
    const float* c1b = (const float*)d_in[5];
    const float* c2w = (const float*)d_in[6];
    const float* c2b = (const float*)d_in[7];
    const float* fvw = (const float*)d_in[8];
    const float* fvb = (const float*)d_in[9];
    const float* emb = (const float*)d_in[10];
    const float* wih = (const float*)d_in[11];
    const float* whh = (const float*)d_in[12];
    const float* bih = (const float*)d_in[13];
    const float* bhh = (const float*)d_in[14];
    const float* wqw = (const float*)d_in[15];
    const float* wqb = (const float*)d_in[16];
    const float* wkw = (const float*)d_in[17];
    const float* wkb = (const float*)d_in[18];
    const float* wvw = (const float*)d_in[19];
    const float* wvb = (const float*)d_in[20];
    const float* aow = (const float*)d_in[21];
    const float* aob = (const float*)d_in[22];
    const float* fqw = (const float*)d_in[23];
    const float* fqb = (const float*)d_in[24];

    float* qout = (float*)d_out;
    float* nh   = qout + NB * 5;

    float *pc1, *pflat, *pfvwp, *pfeat, *pgi, *pgh, *pQ, *pK, *pV, *pctx, *pswarm, *pOp, *plp;
    __nv_bfloat16 *pKb, *pVb;
    cudaGetSymbolAddress((void**)&pc1,    g_conv1);
    cudaGetSymbolAddress((void**)&pflat,  g_flat);
    cudaGetSymbolAddress((void**)&pfvwp,  g_fvwp);
    cudaGetSymbolAddress((void**)&pfeat,  g_feat);
    cudaGetSymbolAddress((void**)&pgi,    g_gi);
    cudaGetSymbolAddress((void**)&pgh,    g_gh);
    cudaGetSymbolAddress((void**)&pQ,     g_Q);
    cudaGetSymbolAddress((void**)&pK,     g_K);
    cudaGetSymbolAddress((void**)&pV,     g_V);
    cudaGetSymbolAddress((void**)&pctx,   g_ctx);
    cudaGetSymbolAddress((void**)&pswarm, g_swarm);
    cudaGetSymbolAddress((void**)&pKb,    g_Kb);
    cudaGetSymbolAddress((void**)&pVb,    g_Vb);
    cudaGetSymbolAddress((void**)&pOp,    g_Opart);
    cudaGetSymbolAddress((void**)&plp,    g_lpart);

    k_flag_init<<<1, 1>>>();
    k_flag_detect<<<16, 256>>>(cls);

    // fc_vis weight permute (matches conv2's [px][oc] flat layout)
    k_permw<<<(HD * FLAT) / 256, 256>>>(fvw, pfvwp);

    // CNN encoder (NHWC intermediate)
    k_conv1<<<(NB * H1 * 6) / 256, 256>>>(img, c1w, c1b, pc1);    // 3456 blocks, 3px/thread
    k_conv2<<<(NB * H2 * 4) / 256, 256>>>(pc1, c2w, c2b, pflat);  // 1024 blocks, 2px/thread

    // vis_feat = relu(flat @ fvwp^T + b) into g_feat[:, :128]
    { dim3 g(128 / 64, NB / 128); k_gemm128<<<g, 256>>>(pflat, FLAT, pfvwp, FLAT, fvb, pfeat, FEAT, FLAT, 1); }
    k_embed<<<(NB * 16) / 256, 256>>>(cls, emb, pfeat);

    // GRU
    { dim3 g(G3H / 64, NB / 128); k_gemm128<<<g, 256>>>(pfeat, FEAT, wih, FEAT, bih, pgi, G3H, FEAT, 0); }
    { dim3 g(G3H / 64, NB / 128); k_gemm128<<<g, 256>>>(h0,    HD,   whh, HD,   bhh, pgh, G3H, HD,   0); }
    k_gru<<<(NB * HD) / 256, 256>>>(pgi, pgh, h0, nh);

    // Q, K, V projections (fp32)
    { dim3 g(HD / 64, NB / 128); k_gemm128<<<g, 256>>>(nh, HD, wqw, HD, wqb, pQ, HD, HD, 0); }
    { dim3 g(HD / 64, NB / 128); k_gemm128<<<g, 256>>>(nh, HD, wkw, HD, wkb, pK, HD, HD, 0); }
    { dim3 g(HD / 64, NB / 128); k_gemm128<<<g, 256>>>(nh, HD, wvw, HD, wvb, pV, HD, HD, 0); }

    // bf16 prep
    k_cvtbf<<<(NB * HD / 2) / 256, 256>>>(pK, pKb);
    k_cvtbf<<<(NB * HD / 2) / 256, 256>>>(pV, pVb);

    // mma.sync flash attention
    const int attn_smem = 65536;
    cudaFuncSetAttribute(k_attn_mma, cudaFuncAttributeMaxDynamicSharedMemorySize, attn_smem);
    k_attn_mma<<<128, 256, attn_smem>>>(pQ, pKb, pVb, adj, pOp, plp);
    k_merge<<<(NB * HD) / 256, 256>>>(pOp, plp, pctx);

    // attention output projection
    { dim3 g(HD / 64, NB / 128); k_gemm128<<<g, 256>>>(pctx, HD, aow, HD, aob, pswarm, HD, HD, 0); }

    k_fcq<<<(NB * 5 + 255) / 256, 256>>>(nh, pswarm, fqw, fqb, qout);
}

// round 14
// speedup vs baseline: 1.1206x; 1.1206x over previous
#include <cuda_runtime.h>
#include <cuda_bf16.h>
#include <cstdint>
#include <math.h>

// ---------------- problem dims ----------------
#define NB    8192
#define HD    128
#define H1    18
#define H2    8
#define FLAT  2048
#define FEAT  144
#define G3H   384

// ---------------- scratch ----------------
__device__ float g_conv1[NB * 16 * H1 * H1];
__device__ float g_flat [NB * FLAT];
__device__ float g_feat [NB * FEAT];
__device__ float g_gi   [NB * G3H];
__device__ float g_gh   [NB * G3H];
__device__ float g_Q    [NB * HD];
__device__ float g_K    [NB * HD];
__device__ float g_V    [NB * HD];
__device__ float g_ctx  [NB * HD];
__device__ float g_swarm[NB * HD];
__device__ __nv_bfloat16 g_Kb[NB * HD];
__device__ __nv_bfloat16 g_Vb[NB * HD];
__device__ float g_Opart[2 * NB * HD];
__device__ float g_lpart[2 * NB];
__device__ int   g_isI32;

// ---------------- packed fp32x2 FMA (Blackwell base ISA, exact fp32) ----------------
typedef unsigned long long ull;
#define FMA2(d, a, b) \
    asm("fma.rn.f32x2 %0, %1, %2, %0;" : "+l"(d) : "l"(a), "l"(b))
__device__ __forceinline__ ull pk2(float x, float y) {
    ull r; asm("mov.b64 %0, {%1, %2};" : "=l"(r) : "f"(x), "f"(y)); return r;
}
__device__ __forceinline__ float2 upk2(ull v) {
    float2 f; asm("mov.b64 {%0, %1}, %2;" : "=f"(f.x), "=f"(f.y) : "l"(v)); return f;
}

// ---------------- mma/ldmatrix helpers (base ISA, legal on sm_103) ----------------
__device__ __forceinline__ uint32_t smem_u32(const void* p) {
    uint32_t a;
    asm("{ .reg .u64 t; cvta.to.shared.u64 t, %1; cvt.u32.u64 %0, t; }" : "=r"(a) : "l"(p));
    return a;
}
#define LDSM_X4(r0, r1, r2, r3, a) \
    asm volatile("ldmatrix.sync.aligned.m8n8.x4.shared.b16 {%0,%1,%2,%3}, [%4];" \
        : "=r"(r0), "=r"(r1), "=r"(r2), "=r"(r3) : "r"(a))
#define LDSM_X4T(r0, r1, r2, r3, a) \
    asm volatile("ldmatrix.sync.aligned.m8n8.x4.trans.shared.b16 {%0,%1,%2,%3}, [%4];" \
        : "=r"(r0), "=r"(r1), "=r"(r2), "=r"(r3) : "r"(a))
#define MMA_BF16(d, a, b0, b1) \
    asm volatile("mma.sync.aligned.m16n8k16.row.col.f32.bf16.bf16.f32 " \
        "{%0,%1,%2,%3}, {%4,%5,%6,%7}, {%8,%9}, {%0,%1,%2,%3};" \
        : "+f"((d)[0]), "+f"((d)[1]), "+f"((d)[2]), "+f"((d)[3]) \
        : "r"((a)[0]), "r"((a)[1]), "r"((a)[2]), "r"((a)[3]), "r"(b0), "r"(b1))

__device__ __forceinline__ uint32_t packbf(float x, float y) {
    __nv_bfloat162 h = __floats2bfloat162_rn(x, y);
    return *(uint32_t*)&h;
}

// ---------------- class_ids dtype detection ----------------
__global__ void k_flag_init() { g_isI32 = 0; }
__global__ void k_flag_detect(const int* __restrict__ p) {
    int i = blockIdx.x * blockDim.x + threadIdx.x;
    if (i < 4096 && p[2 * i + 1] != 0) g_isI32 = 1;
}

// ---------------- conv1: 3 pixels per thread, 16 oc, f32x2 FMA, float2 loads ----------------
__global__ void k_conv1(const float* __restrict__ img, const float* __restrict__ w,
                        const float* __restrict__ b, float* __restrict__ out) {
    __shared__ float ws[75 * 16];   // [k][oc]
    __shared__ float bs[16];
    for (int i = threadIdx.x; i < 1200; i += 256) {
        int oc = i / 75, k = i % 75;
        ws[k * 16 + oc] = w[i];
    }
    if (threadIdx.x < 16) bs[threadIdx.x] = b[threadIdx.x];
    __syncthreads();

    int idx = blockIdx.x * 256 + threadIdx.x;   // 8192*18*6 items
    int g  = idx % 6;
    int oy = (idx / 6) % H1;
    int n  = idx / (6 * H1);
    int ox0 = g * 3;
    const float* ip = img + (size_t)n * 4800;

    ull acc[3][8];                  // 3 px x 8 oc-pairs
    #pragma unroll
    for (int p = 0; p < 3; p++)
        #pragma unroll
        for (int q = 0; q < 8; q++) acc[p][q] = pk2(bs[2 * q], bs[2 * q + 1]);

    #pragma unroll
    for (int ic = 0; ic < 3; ic++) {
        #pragma unroll
        for (int ky = 0; ky < 5; ky++) {
            // offset = ic*1600 + (2oy+ky)*40 + 6g : always even -> 8B aligned
            const float* row = ip + ic * 1600 + (2 * oy + ky) * 40 + ox0 * 2;
            float rv[9];
            float2 t0 = *(const float2*)(row);
            float2 t1 = *(const float2*)(row + 2);
            float2 t2 = *(const float2*)(row + 4);
            float2 t3 = *(const float2*)(row + 6);
            rv[0] = t0.x; rv[1] = t0.y; rv[2] = t1.x; rv[3] = t1.y;
            rv[4] = t2.x; rv[5] = t2.y; rv[6] = t3.x; rv[7] = t3.y;
            rv[8] = row[8];
            #pragma unroll
            for (int kx = 0; kx < 5; kx++) {
                const ulonglong2* wp = (const ulonglong2*)&ws[((ic * 5 + ky) * 5 + kx) * 16];
                ulonglong2 w0 = wp[0], w1 = wp[1], w2 = wp[2], w3 = wp[3];
                #pragma unroll
                for (int p = 0; p < 3; p++) {
                    ull vv = pk2(rv[2 * p + kx], rv[2 * p + kx]);
                    FMA2(acc[p][0], vv, w0.x); FMA2(acc[p][1], vv, w0.y);
                    FMA2(acc[p][2], vv, w1.x); FMA2(acc[p][3], vv, w1.y);
                    FMA2(acc[p][4], vv, w2.x); FMA2(acc[p][5], vv, w2.y);
                    FMA2(acc[p][6], vv, w3.x); FMA2(acc[p][7], vv, w3.y);
                }
            }
        }
    }
    float* op = out + (size_t)n * (16 * 324) + oy * H1 + ox0;
    #pragma unroll
    for (int q = 0; q < 8; q++)
        #pragma unroll
        for (int p = 0; p < 3; p++) {
            float2 v = upk2(acc[p][q]);
            op[(2 * q) * 324 + p]     = fmaxf(v.x, 0.f);
            op[(2 * q + 1) * 324 + p] = fmaxf(v.y, 0.f);
        }
}

// ---------------- conv2: 2 pixels per thread, 32 oc, 2 CTAs/SM, f32x2, float2 loads ----------------
__global__ void __launch_bounds__(256, 2)
k_conv2(const float* __restrict__ in, const float* __restrict__ w,
        const float* __restrict__ b, float* __restrict__ out) {
    __shared__ float ws[144 * 32];  // [k][oc]
    __shared__ float bs[32];
    for (int i = threadIdx.x; i < 4608; i += 256) {
        int oc = i / 144, k = i % 144;
        ws[k * 32 + oc] = w[i];
    }
    if (threadIdx.x < 32) bs[threadIdx.x] = b[threadIdx.x];
    __syncthreads();

    int idx = blockIdx.x * 256 + threadIdx.x;   // 8192*8*4 items
    int g  = idx & 3;                           // 2-pixel group
    int oy = (idx >> 2) & 7;
    int n  = idx >> 5;
    int ox0 = g * 2;
    const float* ip = in + (size_t)n * (16 * 324);

    ull acc[2][16];                 // 2 px x 16 oc-pairs
    #pragma unroll
    for (int p = 0; p < 2; p++)
        #pragma unroll
        for (int q = 0; q < 16; q++) acc[p][q] = pk2(bs[2 * q], bs[2 * q + 1]);

    #pragma unroll 2
    for (int ic = 0; ic < 16; ic++) {
        #pragma unroll
        for (int ky = 0; ky < 3; ky++) {
            // offset = ic*324 + (2oy+ky)*18 + 4g : always even -> 8B aligned
            const float* row = ip + ic * 324 + (2 * oy + ky) * H1 + ox0 * 2;
            float rv[5];
            float2 t0 = *(const float2*)(row);
            float2 t1 = *(const float2*)(row + 2);
            rv[0] = t0.x; rv[1] = t0.y; rv[2] = t1.x; rv[3] = t1.y;
            rv[4] = row[4];
            #pragma unroll
            for (int kx = 0; kx < 3; kx++) {
                const ulonglong2* wp = (const ulonglong2*)&ws[(ic * 9 + ky * 3 + kx) * 32];
                ull vv0 = pk2(rv[kx], rv[kx]);
                ull vv1 = pk2(rv[2 + kx], rv[2 + kx]);
                #pragma unroll
                for (int q = 0; q < 8; q++) {
                    ulonglong2 wv = wp[q];
                    FMA2(acc[0][2 * q],     vv0, wv.x);
                    FMA2(acc[0][2 * q + 1], vv0, wv.y);
                    FMA2(acc[1][2 * q],     vv1, wv.x);
                    FMA2(acc[1][2 * q + 1], vv1, wv.y);
                }
            }
        }
    }
    float* op = out + (size_t)n * FLAT + oy * H2 + ox0;
    #pragma unroll
    for (int q = 0; q < 16; q++)
        #pragma unroll
        for (int p = 0; p < 2; p++) {
            float2 v = upk2(acc[p][q]);
            op[(2 * q) * 64 + p]     = fmaxf(v.x, 0.f);
            op[(2 * q + 1) * 64 + p] = fmaxf(v.y, 0.f);
        }
}

// ------- fp32 SGEMM: C[M,N] = act(A[M,K] @ B[N,K]^T + bias), 128x64 tile, BK=16, f32x2 -------
__global__ void __launch_bounds__(256, 2)
k_gemm128(const float* __restrict__ A, int lda,
          const float* __restrict__ B, int ldb,
          const float* __restrict__ bias,
          float* __restrict__ C, int ldc,
          int K, int act) {
    __shared__ float As[16][132];
    __shared__ float Bs[16][68];
    int m0 = blockIdx.y * 128, n0 = blockIdx.x * 64;
    int tid = threadIdx.x;
    int ra = tid >> 1, ka = (tid & 1) * 8;
    int rb = tid >> 2, kb = (tid & 3) * 4;
    int tr = tid >> 4, tc = tid & 15;

    ull acc[8][2];
    #pragma unroll
    for (int i = 0; i < 8; i++) { acc[i][0] = pk2(0.f, 0.f); acc[i][1] = pk2(0.f, 0.f); }

    const float* Ap = A + (size_t)(m0 + ra) * lda + ka;
    const float* Bp = B + (size_t)(n0 + rb) * ldb + kb;

    for (int k0 = 0; k0 < K; k0 += 16) {
        float4 a0 = *(const float4*)(Ap + k0);
        float4 a1 = *(const float4*)(Ap + k0 + 4);
        float4 bv = *(const float4*)(Bp + k0);
        As[ka + 0][ra] = a0.x; As[ka + 1][ra] = a0.y; As[ka + 2][ra] = a0.z; As[ka + 3][ra] = a0.w;
        As[ka + 4][ra] = a1.x; As[ka + 5][ra] = a1.y; As[ka + 6][ra] = a1.z; As[ka + 7][ra] = a1.w;
        Bs[kb + 0][rb] = bv.x; Bs[kb + 1][rb] = bv.y; Bs[kb + 2][rb] = bv.z; Bs[kb + 3][rb] = bv.w;
        __syncthreads();
        #pragma unroll
        for (int k = 0; k < 16; k++) {
            float4 x0 = *(const float4*)&As[k][tr * 4];
            float4 x1 = *(const float4*)&As[k][tr * 4 + 64];
            ulonglong2 yv = *(const ulonglong2*)&Bs[k][tc * 4];
            ull v;
            v = pk2(x0.x, x0.x); FMA2(acc[0][0], v, yv.x); FMA2(acc[0][1], v, yv.y);
            v = pk2(x0.y, x0.y); FMA2(acc[1][0], v, yv.x); FMA2(acc[1][1], v, yv.y);
            v = pk2(x0.z, x0.z); FMA2(acc[2][0], v, yv.x); FMA2(acc[2][1], v, yv.y);
            v = pk2(x0.w, x0.w); FMA2(acc[3][0], v, yv.x); FMA2(acc[3][1], v, yv.y);
            v = pk2(x1.x, x1.x); FMA2(acc[4][0], v, yv.x); FMA2(acc[4][1], v, yv.y);
            v = pk2(x1.y, x1.y); FMA2(acc[5][0], v, yv.x); FMA2(acc[5][1], v, yv.y);
            v = pk2(x1.z, x1.z); FMA2(acc[6][0], v, yv.x); FMA2(acc[6][1], v, yv.y);
            v = pk2(x1.w, x1.w); FMA2(acc[7][0], v, yv.x); FMA2(acc[7][1], v, yv.y);
        }
        __syncthreads();
    }

    float bb[4];
    #pragma unroll
    for (int j = 0; j < 4; j++) bb[j] = bias[n0 + tc * 4 + j];
    #pragma unroll
    for (int i = 0; i < 8; i++) {
        int row = m0 + tr * 4 + (i & 3) + (i >> 2) * 64;
        float2 p0 = upk2(acc[i][0]);
        float2 p1 = upk2(acc[i][1]);
        float4 o;
        o.x = p0.x + bb[0]; o.y = p0.y + bb[1];
        o.z = p1.x + bb[2]; o.w = p1.y + bb[3];
        if (act == 1) {
            o.x = fmaxf(o.x, 0.f); o.y = fmaxf(o.y, 0.f);
            o.z = fmaxf(o.z, 0.f); o.w = fmaxf(o.w, 0.f);
        }
        *(float4*)(C + (size_t)row * ldc + n0 + tc * 4) = o;
    }
}

// ---------------- embedding ----------------
__global__ void k_embed(const int* __restrict__ cls, const float* __restrict__ table,
                        float* __restrict__ feat) {
    int idx = blockIdx.x * 256 + threadIdx.x;
    if (idx >= NB * 16) return;
    int i = idx >> 4, j = idx & 15;
    int id = g_isI32 ? cls[i] : cls[2 * i];
    feat[i * FEAT + 128 + j] = table[id * 16 + j];
}

// ---------------- GRU ----------------
__global__ void k_gru(const float* __restrict__ gi, const float* __restrict__ gh,
                      const float* __restrict__ h, float* __restrict__ nh) {
    int idx = blockIdx.x * 256 + threadIdx.x;
    if (idx >= NB * HD) return;
    int i = idx >> 7, j = idx & 127;
    const float* a = gi + i * G3H;
    const float* c = gh + i * G3H;
    float r = 1.f / (1.f + __expf(-(a[j] + c[j])));
    float z = 1.f / (1.f + __expf(-(a[128 + j] + c[128 + j])));
    float n = tanhf(a[256 + j] + r * c[256 + j]);
    nh[idx] = (1.f - z) * n + z * h[idx];
}

// ---------------- fp32 -> bf16 convert (K and V fused) ----------------
__global__ void k_cvtbf2(const float* __restrict__ X1, __nv_bfloat16* __restrict__ Y1,
                         const float* __restrict__ X2, __nv_bfloat16* __restrict__ Y2) {
    int i = blockIdx.x * 256 + threadIdx.x;   // pairs
    float2 a = ((const float2*)X1)[i];
    float2 b = ((const float2*)X2)[i];
    ((__nv_bfloat162*)Y1)[i] = __floats2bfloat162_rn(a.x, a.y);
    ((__nv_bfloat162*)Y2)[i] = __floats2bfloat162_rn(b.x, b.y);
}

// ============ mma.sync bf16 flash attention (split-KV over 2 halves) ============
__global__ void __launch_bounds__(256, 1)
k_attn_mma(const float* __restrict__ Qf, const __nv_bfloat16* __restrict__ Kb,
           const __nv_bfloat16* __restrict__ Vb, const int* __restrict__ adj,
           float* __restrict__ Opart, float* __restrict__ lpart) {
    extern __shared__ char smem[];
    char* Ks = smem;            // 128 rows x 256B (swizzled)
    char* Vs = smem + 32768;
    uint32_t KsA = smem_u32(Ks);
    uint32_t VsA = smem_u32(Vs);

    int tid  = threadIdx.x;
    int wid  = tid >> 5;
    int lane = tid & 31;
    int m    = lane >> 3;
    int row0 = (blockIdx.x & 63) * 128;
    int half = blockIdx.x >> 6;
    int cst  = half * 4096;
    const float scale = 0.08838834764831845f;

    #pragma unroll
    for (int it = 0; it < 8; it++) {
        int id = tid + it * 256;
        int r = id >> 4, u = id & 15;
        const float4* qp = (const float4*)(Qf + (size_t)(row0 + r) * 128 + u * 8);
        float4 v0 = qp[0], v1 = qp[1];
        uint32_t pk[4] = { packbf(v0.x, v0.y), packbf(v0.z, v0.w),
                           packbf(v1.x, v1.y), packbf(v1.z, v1.w) };
        *(int4*)(Ks + r * 256 + ((u ^ (r & 7)) * 16)) = *(int4*)pk;
    }
    __syncthreads();

    uint32_t qf[8][4];
    #pragma unroll
    for (int kk = 0; kk < 8; kk++) {
        int r = wid * 16 + (m & 1) * 8 + (lane & 7);
        int u = kk * 2 + (m >> 1);
        uint32_t a = KsA + r * 256 + ((u ^ (r & 7)) * 16);
        LDSM_X4(qf[kk][0], qf[kk][1], qf[kk][2], qf[kk][3], a);
    }
    __syncthreads();

    float oacc[16][4];
    #pragma unroll
    for (int j = 0; j < 16; j++)
        #pragma unroll
        for (int i = 0; i < 4; i++) oacc[j][i] = 0.f;
    float lsum0 = 0.f, lsum1 = 0.f;

    int grow0 = row0 + wid * 16 + (lane >> 2);
    const int* adjr0 = adj + (size_t)grow0 * NB;
    const int* adjr1 = adjr0 + (size_t)8 * NB;

    for (int t = 0; t < 32; t++) {
        int c0 = cst + t * 128;
        #pragma unroll
        for (int it = 0; it < 8; it++) {
            int id = tid + it * 256;
            int r = id >> 4, u = id & 15;
            int4 kv = *(const int4*)(Kb + (size_t)(c0 + r) * 128 + u * 8);
            int4 vv = *(const int4*)(Vb + (size_t)(c0 + r) * 128 + u * 8);
            int off = r * 256 + ((u ^ (r & 7)) * 16);
            *(int4*)(Ks + off) = kv;
            *(int4*)(Vs + off) = vv;
        }
        __syncthreads();

        float sacc[16][4];
        #pragma unroll
        for (int j = 0; j < 16; j++)
            #pragma unroll
            for (int i = 0; i < 4; i++) sacc[j][i] = 0.f;

        #pragma unroll
        for (int kk = 0; kk < 8; kk++) {
            #pragma unroll
            for (int jp = 0; jp < 8; jp++) {
                int nr = jp * 16 + (m >> 1) * 8 + (lane & 7);
                int u  = kk * 2 + (m & 1);
                uint32_t a = KsA + nr * 256 + ((u ^ (nr & 7)) * 16);
                uint32_t b0, b1, b2, b3;
                LDSM_X4(b0, b1, b2, b3, a);
                MMA_BF16(sacc[2 * jp],     qf[kk], b0, b1);
                MMA_BF16(sacc[2 * jp + 1], qf[kk], b2, b3);
            }
        }

        uint32_t pf[8][4];
        int cb = c0 + (lane & 3) * 2;
        #pragma unroll
        for (int s = 0; s < 8; s++) {
            int ca = cb + s * 16;
            int cbb = ca + 8;
            int2 m00 = *(const int2*)(adjr0 + ca);
            int2 m01 = *(const int2*)(adjr1 + ca);
            int2 m10 = *(const int2*)(adjr0 + cbb);
            int2 m11 = *(const int2*)(adjr1 + cbb);
            float p00 = m00.x ? __expf(sacc[2 * s][0] * scale) : 0.f;
            float p01 = m00.y ? __expf(sacc[2 * s][1] * scale) : 0.f;
            float p02 = m01.x ? __expf(sacc[2 * s][2] * scale) : 0.f;
            float p03 = m01.y ? __expf(sacc[2 * s][3] * scale) : 0.f;
            float p10 = m10.x ? __expf(sacc[2 * s + 1][0] * scale) : 0.f;
            float p11 = m10.y ? __expf(sacc[2 * s + 1][1] * scale) : 0.f;
            float p12 = m11.x ? __expf(sacc[2 * s + 1][2] * scale) : 0.f;
            float p13 = m11.y ? __expf(sacc[2 * s + 1][3] * scale) : 0.f;
            lsum0 += (p00 + p01) + (p10 + p11);
            lsum1 += (p02 + p03) + (p12 + p13);
            pf[s][0] = packbf(p00, p01);
            pf[s][1] = packbf(p02, p03);
            pf[s][2] = packbf(p10, p11);
            pf[s][3] = packbf(p12, p13);
        }

        #pragma unroll
        for (int sp = 0; sp < 4; sp++) {
            #pragma unroll
            for (int jj = 0; jj < 16; jj++) {
                int cr = sp * 32 + m * 8 + (lane & 7);
                uint32_t a = VsA + cr * 256 + ((jj ^ (cr & 7)) * 16);
                uint32_t b0, b1, b2, b3;
                LDSM_X4T(b0, b1, b2, b3, a);
                MMA_BF16(oacc[jj], pf[2 * sp],     b0, b1);
                MMA_BF16(oacc[jj], pf[2 * sp + 1], b2, b3);
            }
        }
        __syncthreads();
    }

    lsum0 += __shfl_xor_sync(0xffffffffu, lsum0, 1);
    lsum0 += __shfl_xor_sync(0xffffffffu, lsum0, 2);
    lsum1 += __shfl_xor_sync(0xffffffffu, lsum1, 1);
    lsum1 += __shfl_xor_sync(0xffffffffu, lsum1, 2);
    if ((lane & 3) == 0) {
        lpart[half * NB + grow0]     = lsum0;
        lpart[half * NB + grow0 + 8] = lsum1;
    }
    float* o0 = Opart + ((size_t)half * NB + grow0) * 128 + (lane & 3) * 2;
    float* o1 = o0 + (size_t)8 * 128;
    #pragma unroll
    for (int jj = 0; jj < 16; jj++) {
        *(float2*)(o0 + jj * 8) = make_float2(oacc[jj][0], oacc[jj][1]);
        *(float2*)(o1 + jj * 8) = make_float2(oacc[jj][2], oacc[jj][3]);
    }
}

// ---------------- merge split-KV halves ----------------
__global__ void k_merge(const float* __restrict__ O, const float* __restrict__ l,
                        float* __restrict__ ctx) {
    int idx = blockIdx.x * 256 + threadIdx.x;
    int r = idx >> 7;
    float denom = l[r] + l[NB + r];
    ctx[idx] = (O[idx] + O[NB * HD + idx]) / denom;
}

// ---------------- final head ----------------
__global__ void k_fcq(const float* __restrict__ nh, const float* __restrict__ sw,
                      const float* __restrict__ W, const float* __restrict__ b,
                      float* __restrict__ q) {
    int idx = blockIdx.x * 256 + threadIdx.x;
    if (idx >= NB * 5) return;
    int i = idx / 5, a = idx % 5;
    const float* w = W + a * 256;
    const float* hr = nh + i * 128;
    const float* sr = sw + i * 128;
    float s = b[a];
    #pragma unroll 8
    for (int k = 0; k < 128; k++) s += hr[k] * w[k];
    #pragma unroll 8
    for (int k = 0; k < 128; k++) s += sr[k] * w[128 + k];
    q[idx] = s;
}

// ---------------- launch ----------------
extern "C" void kernel_launch(void* const* d_in, const int* in_sizes, int n_in,
                              void* d_out, int out_size) {
    const float* img = (const float*)d_in[0];
    const int*   adj = (const int*)  d_in[1];
    const int*   cls = (const int*)  d_in[2];
    const float* h0  = (const float*)d_in[3];
    const float* c1w = (const float*)d_in[4];
    const float* c1b = (const float*)d_in[5];
    const float* c2w = (const float*)d_in[6];
    const float* c2b = (const float*)d_in[7];
    const float* fvw = (const float*)d_in[8];
    const float* fvb = (const float*)d_in[9];
    const float* emb = (const float*)d_in[10];
    const float* wih = (const float*)d_in[11];
    const float* whh = (const float*)d_in[12];
    const float* bih = (const float*)d_in[13];
    const float* bhh = (const float*)d_in[14];
    const float* wqw = (const float*)d_in[15];
    const float* wqb = (const float*)d_in[16];
    const float* wkw = (const float*)d_in[17];
    const float* wkb = (const float*)d_in[18];
    const float* wvw = (const float*)d_in[19];
    const float* wvb = (const float*)d_in[20];
    const float* aow = (const float*)d_in[21];
    const float* aob = (const float*)d_in[22];
    const float* fqw = (const float*)d_in[23];
    const float* fqb = (const float*)d_in[24];

    float* qout = (float*)d_out;
    float* nh   = qout + NB * 5;

    float *pc1, *pflat, *pfeat, *pgi, *pgh, *pQ, *pK, *pV, *pctx, *pswarm, *pOp, *plp;
    __nv_bfloat16 *pKb, *pVb;
    cudaGetSymbolAddress((void**)&pc1,    g_conv1);
    cudaGetSymbolAddress((void**)&pflat,  g_flat);
    cudaGetSymbolAddress((void**)&pfeat,  g_feat);
    cudaGetSymbolAddress((void**)&pgi,    g_gi);
    cudaGetSymbolAddress((void**)&pgh,    g_gh);
    cudaGetSymbolAddress((void**)&pQ,     g_Q);
    cudaGetSymbolAddress((void**)&pK,     g_K);
    cudaGetSymbolAddress((void**)&pV,     g_V);
    cudaGetSymbolAddress((void**)&pctx,   g_ctx);
    cudaGetSymbolAddress((void**)&pswarm, g_swarm);
    cudaGetSymbolAddress((void**)&pKb,    g_Kb);
    cudaGetSymbolAddress((void**)&pVb,    g_Vb);
    cudaGetSymbolAddress((void**)&pOp,    g_Opart);
    cudaGetSymbolAddress((void**)&plp,    g_lpart);

    k_flag_init<<<1, 1>>>();
    k_flag_detect<<<16, 256>>>(cls);

    // CNN encoder (NCHW, f32x2)
    k_conv1<<<(NB * H1 * 6) / 256, 256>>>(img, c1w, c1b, pc1);    // 3456 blocks, 3px/thread
    k_conv2<<<(NB * H2 * 4) / 256, 256>>>(pc1, c2w, c2b, pflat);  // 1024 blocks, 2px/thread

    // vis_feat = relu(flat @ fc_vis_w^T + b) into g_feat[:, :128]
    { dim3 g(128 / 64, NB / 128); k_gemm128<<<g, 256>>>(pflat, FLAT, fvw, FLAT, fvb, pfeat, FEAT, FLAT, 1); }
    k_embed<<<(NB * 16) / 256, 256>>>(cls, emb, pfeat);

    // GRU
    { dim3 g(G3H / 64, NB / 128); k_gemm128<<<g, 256>>>(pfeat, FEAT, wih, FEAT, bih, pgi, G3H, FEAT, 0); }
    { dim3 g(G3H / 64, NB / 128); k_gemm128<<<g, 256>>>(h0,    HD,   whh, HD,   bhh, pgh, G3H, HD,   0); }
    k_gru<<<(NB * HD) / 256, 256>>>(pgi, pgh, h0, nh);

    // Q, K, V projections (fp32)
    { dim3 g(HD / 64, NB / 128); k_gemm128<<<g, 256>>>(nh, HD, wqw, HD, wqb, pQ, HD, HD, 0); }
    { dim3 g(HD / 64, NB / 128); k_gemm128<<<g, 256>>>(nh, HD, wkw, HD, wkb, pK, HD, HD, 0); }
    { dim3 g(HD / 64, NB / 128); k_gemm128<<<g, 256>>>(nh, HD, wvw, HD, wvb, pV, HD, HD, 0); }

    // bf16 prep (fused K+V)
    k_cvtbf2<<<(NB * HD / 2) / 256, 256>>>(pK, pKb, pV, pVb);

    // mma.sync flash attention
    const int attn_smem = 65536;
    cudaFuncSetAttribute(k_attn_mma, cudaFuncAttributeMaxDynamicSharedMemorySize, attn_smem);
    k_attn_mma<<<128, 256, attn_smem>>>(pQ, pKb, pVb, adj, pOp, plp);
    k_merge<<<(NB * HD) / 256, 256>>>(pOp, plp, pctx);

    // attention output projection
    { dim3 g(HD / 64, NB / 128); k_gemm128<<<g, 256>>>(pctx, HD, aow, HD, aob, pswarm, HD, HD, 0); }

    k_fcq<<<(NB * 5 + 255) / 256, 256>>>(nh, pswarm, fqw, fqb, qout);
}

// round 15
// speedup vs baseline: 1.1210x; 1.0004x over previous
#include <cuda_runtime.h>
#include <cuda_bf16.h>
#include <cstdint>
#include <math.h>

// ---------------- problem dims ----------------
#define NB    8192
#define HD    128
#define H1    18
#define H2    8
#define FLAT  2048
#define FEAT  144
#define G3H   384

// ---------------- scratch ----------------
__device__ float g_conv1[NB * 16 * H1 * H1];
__device__ float g_flat [NB * FLAT];
__device__ float g_feat [NB * FEAT];
__device__ float g_gi   [NB * G3H];
__device__ float g_gh   [NB * G3H];
__device__ float g_Q    [NB * HD];
__device__ float g_K    [NB * HD];
__device__ float g_V    [NB * HD];
__device__ float g_ctx  [NB * HD];
__device__ float g_swarm[NB * HD];
__device__ __nv_bfloat16 g_Kb[NB * HD];
__device__ __nv_bfloat16 g_Vb[NB * HD];
__device__ float g_Opart[2 * NB * HD];
__device__ float g_lpart[2 * NB];
__device__ int   g_isI32;

// ---------------- packed fp32x2 FMA (Blackwell base ISA, exact fp32) ----------------
typedef unsigned long long ull;
#define FMA2(d, a, b) \
    asm("fma.rn.f32x2 %0, %1, %2, %0;" : "+l"(d) : "l"(a), "l"(b))
__device__ __forceinline__ ull pk2(float x, float y) {
    ull r; asm("mov.b64 %0, {%1, %2};" : "=l"(r) : "f"(x), "f"(y)); return r;
}
__device__ __forceinline__ float2 upk2(ull v) {
    float2 f; asm("mov.b64 {%0, %1}, %2;" : "=f"(f.x), "=f"(f.y) : "l"(v)); return f;
}

// ---------------- mma/ldmatrix helpers (base ISA, legal on sm_103) ----------------
__device__ __forceinline__ uint32_t smem_u32(const void* p) {
    uint32_t a;
    asm("{ .reg .u64 t; cvta.to.shared.u64 t, %1; cvt.u32.u64 %0, t; }" : "=r"(a) : "l"(p));
    return a;
}
#define LDSM_X4(r0, r1, r2, r3, a) \
    asm volatile("ldmatrix.sync.aligned.m8n8.x4.shared.b16 {%0,%1,%2,%3}, [%4];" \
        : "=r"(r0), "=r"(r1), "=r"(r2), "=r"(r3) : "r"(a))
#define LDSM_X4T(r0, r1, r2, r3, a) \
    asm volatile("ldmatrix.sync.aligned.m8n8.x4.trans.shared.b16 {%0,%1,%2,%3}, [%4];" \
        : "=r"(r0), "=r"(r1), "=r"(r2), "=r"(r3) : "r"(a))
#define MMA_BF16(d, a, b0, b1) \
    asm volatile("mma.sync.aligned.m16n8k16.row.col.f32.bf16.bf16.f32 " \
        "{%0,%1,%2,%3}, {%4,%5,%6,%7}, {%8,%9}, {%0,%1,%2,%3};" \
        : "+f"((d)[0]), "+f"((d)[1]), "+f"((d)[2]), "+f"((d)[3]) \
        : "r"((a)[0]), "r"((a)[1]), "r"((a)[2]), "r"((a)[3]), "r"(b0), "r"(b1))

__device__ __forceinline__ uint32_t packbf(float x, float y) {
    __nv_bfloat162 h = __floats2bfloat162_rn(x, y);
    return *(uint32_t*)&h;
}

// ---------------- class_ids dtype detection ----------------
__global__ void k_flag_init() { g_isI32 = 0; }
__global__ void k_flag_detect(const int* __restrict__ p) {
    int i = blockIdx.x * blockDim.x + threadIdx.x;
    if (i < 4096 && p[2 * i + 1] != 0) g_isI32 = 1;
}

// ---------------- conv1: 3 pixels per thread, 16 oc, f32x2 FMA, float2 loads ----------------
__global__ void k_conv1(const float* __restrict__ img, const float* __restrict__ w,
                        const float* __restrict__ b, float* __restrict__ out) {
    __shared__ float ws[75 * 16];   // [k][oc]
    __shared__ float bs[16];
    for (int i = threadIdx.x; i < 1200; i += 256) {
        int oc = i / 75, k = i % 75;
        ws[k * 16 + oc] = w[i];
    }
    if (threadIdx.x < 16) bs[threadIdx.x] = b[threadIdx.x];
    __syncthreads();

    int idx = blockIdx.x * 256 + threadIdx.x;   // 8192*18*6 items
    int g  = idx % 6;
    int oy = (idx / 6) % H1;
    int n  = idx / (6 * H1);
    int ox0 = g * 3;
    const float* ip = img + (size_t)n * 4800;

    ull acc[3][8];                  // 3 px x 8 oc-pairs
    #pragma unroll
    for (int p = 0; p < 3; p++)
        #pragma unroll
        for (int q = 0; q < 8; q++) acc[p][q] = pk2(bs[2 * q], bs[2 * q + 1]);

    #pragma unroll
    for (int ic = 0; ic < 3; ic++) {
        #pragma unroll
        for (int ky = 0; ky < 5; ky++) {
            const float* row = ip + ic * 1600 + (2 * oy + ky) * 40 + ox0 * 2;
            float rv[9];
            float2 t0 = *(const float2*)(row);
            float2 t1 = *(const float2*)(row + 2);
            float2 t2 = *(const float2*)(row + 4);
            float2 t3 = *(const float2*)(row + 6);
            rv[0] = t0.x; rv[1] = t0.y; rv[2] = t1.x; rv[3] = t1.y;
            rv[4] = t2.x; rv[5] = t2.y; rv[6] = t3.x; rv[7] = t3.y;
            rv[8] = row[8];
            #pragma unroll
            for (int kx = 0; kx < 5; kx++) {
                const ulonglong2* wp = (const ulonglong2*)&ws[((ic * 5 + ky) * 5 + kx) * 16];
                ulonglong2 w0 = wp[0], w1 = wp[1], w2 = wp[2], w3 = wp[3];
                #pragma unroll
                for (int p = 0; p < 3; p++) {
                    ull vv = pk2(rv[2 * p + kx], rv[2 * p + kx]);
                    FMA2(acc[p][0], vv, w0.x); FMA2(acc[p][1], vv, w0.y);
                    FMA2(acc[p][2], vv, w1.x); FMA2(acc[p][3], vv, w1.y);
                    FMA2(acc[p][4], vv, w2.x); FMA2(acc[p][5], vv, w2.y);
                    FMA2(acc[p][6], vv, w3.x); FMA2(acc[p][7], vv, w3.y);
                }
            }
        }
    }
    float* op = out + (size_t)n * (16 * 324) + oy * H1 + ox0;
    #pragma unroll
    for (int q = 0; q < 8; q++)
        #pragma unroll
        for (int p = 0; p < 3; p++) {
            float2 v = upk2(acc[p][q]);
            op[(2 * q) * 324 + p]     = fmaxf(v.x, 0.f);
            op[(2 * q + 1) * 324 + p] = fmaxf(v.y, 0.f);
        }
}

// ---------------- conv2: warp-per-image, smem-staged ic-slices, 2 px/thread, f32x2 ----------------
// Each warp handles one image; per ic, the 324-float channel slice is loaded with
// 3 coalesced LDG.128/lane into a warp-private smem buffer (prefetched one ic ahead
// in registers so compute hides the latency). FMA structure identical to R12/R14.
__global__ void __launch_bounds__(256, 2)
k_conv2(const float* __restrict__ in, const float* __restrict__ w,
        const float* __restrict__ b, float* __restrict__ out) {
    __shared__ float ws[144 * 32];      // [k][oc]
    __shared__ float bs[32];
    __shared__ float buf[8][328];       // warp-private ic slice (324 + pad)
    int tid = threadIdx.x;
    int wd = tid >> 5, lane = tid & 31;

    for (int i = tid; i < 4608; i += 256) {
        int oc = i / 144, k = i % 144;
        ws[k * 32 + oc] = w[i];
    }
    if (tid < 32) bs[tid] = b[tid];
    __syncthreads();

    int n = blockIdx.x * 8 + wd;        // grid = NB/8
    int g  = lane & 3;
    int oy = lane >> 2;
    int ox0 = g * 2;
    const float4* ip4 = (const float4*)(in + (size_t)n * (16 * 324));
    float4* bw = (float4*)buf[wd];
    const float* sp = buf[wd];

    ull acc[2][16];
    #pragma unroll
    for (int p = 0; p < 2; p++)
        #pragma unroll
        for (int q = 0; q < 16; q++) acc[p][q] = pk2(bs[2 * q], bs[2 * q + 1]);

    // stage ic = 0
    {
        float4 p0 = ip4[lane];
        float4 p1 = ip4[lane + 32];
        float4 p2 = (lane < 17) ? ip4[lane + 64] : make_float4(0.f, 0.f, 0.f, 0.f);
        bw[lane] = p0; bw[lane + 32] = p1;
        if (lane < 17) bw[lane + 64] = p2;
    }
    __syncwarp();

    for (int ic = 0; ic < 16; ic++) {
        // prefetch next ic slice into registers (latency hidden by compute below)
        float4 p0, p1, p2;
        if (ic < 15) {
            const float4* nx = ip4 + (ic + 1) * 81;
            p0 = nx[lane];
            p1 = nx[lane + 32];
            if (lane < 17) p2 = nx[lane + 64];
        }

        #pragma unroll
        for (int ky = 0; ky < 3; ky++) {
            const float* row = sp + (2 * oy + ky) * H1 + ox0 * 2;
            float rv[5];
            float2 t0 = *(const float2*)(row);
            float2 t1 = *(const float2*)(row + 2);
            rv[0] = t0.x; rv[1] = t0.y; rv[2] = t1.x; rv[3] = t1.y;
            rv[4] = row[4];
            #pragma unroll
            for (int kx = 0; kx < 3; kx++) {
                const ulonglong2* wp = (const ulonglong2*)&ws[(ic * 9 + ky * 3 + kx) * 32];
                ull vv0 = pk2(rv[kx], rv[kx]);
                ull vv1 = pk2(rv[2 + kx], rv[2 + kx]);
                #pragma unroll
                for (int q = 0; q < 8; q++) {
                    ulonglong2 wv = wp[q];
                    FMA2(acc[0][2 * q],     vv0, wv.x);
                    FMA2(acc[0][2 * q + 1], vv0, wv.y);
                    FMA2(acc[1][2 * q],     vv1, wv.x);
                    FMA2(acc[1][2 * q + 1], vv1, wv.y);
                }
            }
        }
        __syncwarp();
        if (ic < 15) {
            bw[lane] = p0; bw[lane + 32] = p1;
            if (lane < 17) bw[lane + 64] = p2;
            __syncwarp();
        }
    }

    float* op = out + (size_t)n * FLAT + oy * H2 + ox0;
    #pragma unroll
    for (int q = 0; q < 16; q++)
        #pragma unroll
        for (int p = 0; p < 2; p++) {
            float2 v = upk2(acc[p][q]);
            op[(2 * q) * 64 + p]     = fmaxf(v.x, 0.f);
            op[(2 * q + 1) * 64 + p] = fmaxf(v.y, 0.f);
        }
}

// ------- fp32 SGEMM: C[M,N] = act(A[M,K] @ B[N,K]^T + bias), 128x64 tile, BK=16, f32x2 -------
__global__ void __launch_bounds__(256, 2)
k_gemm128(const float* __restrict__ A, int lda,
          const float* __restrict__ B, int ldb,
          const float* __restrict__ bias,
          float* __restrict__ C, int ldc,
          int K, int act) {
    __shared__ float As[16][132];
    __shared__ float Bs[16][68];
    int m0 = blockIdx.y * 128, n0 = blockIdx.x * 64;
    int tid = threadIdx.x;
    int ra = tid >> 1, ka = (tid & 1) * 8;
    int rb = tid >> 2, kb = (tid & 3) * 4;
    int tr = tid >> 4, tc = tid & 15;

    ull acc[8][2];
    #pragma unroll
    for (int i = 0; i < 8; i++) { acc[i][0] = pk2(0.f, 0.f); acc[i][1] = pk2(0.f, 0.f); }

    const float* Ap = A + (size_t)(m0 + ra) * lda + ka;
    const float* Bp = B + (size_t)(n0 + rb) * ldb + kb;

    for (int k0 = 0; k0 < K; k0 += 16) {
        float4 a0 = *(const float4*)(Ap + k0);
        float4 a1 = *(const float4*)(Ap + k0 + 4);
        float4 bv = *(const float4*)(Bp + k0);
        As[ka + 0][ra] = a0.x; As[ka + 1][ra] = a0.y; As[ka + 2][ra] = a0.z; As[ka + 3][ra] = a0.w;
        As[ka + 4][ra] = a1.x; As[ka + 5][ra] = a1.y; As[ka + 6][ra] = a1.z; As[ka + 7][ra] = a1.w;
        Bs[kb + 0][rb] = bv.x; Bs[kb + 1][rb] = bv.y; Bs[kb + 2][rb] = bv.z; Bs[kb + 3][rb] = bv.w;
        __syncthreads();
        #pragma unroll
        for (int k = 0; k < 16; k++) {
            float4 x0 = *(const float4*)&As[k][tr * 4];
            float4 x1 = *(const float4*)&As[k][tr * 4 + 64];
            ulonglong2 yv = *(const ulonglong2*)&Bs[k][tc * 4];
            ull v;
            v = pk2(x0.x, x0.x); FMA2(acc[0][0], v, yv.x); FMA2(acc[0][1], v, yv.y);
            v = pk2(x0.y, x0.y); FMA2(acc[1][0], v, yv.x); FMA2(acc[1][1], v, yv.y);
            v = pk2(x0.z, x0.z); FMA2(acc[2][0], v, yv.x); FMA2(acc[2][1], v, yv.y);
            v = pk2(x0.w, x0.w); FMA2(acc[3][0], v, yv.x); FMA2(acc[3][1], v, yv.y);
            v = pk2(x1.x, x1.x); FMA2(acc[4][0], v, yv.x); FMA2(acc[4][1], v, yv.y);
            v = pk2(x1.y, x1.y); FMA2(acc[5][0], v, yv.x); FMA2(acc[5][1], v, yv.y);
            v = pk2(x1.z, x1.z); FMA2(acc[6][0], v, yv.x); FMA2(acc[6][1], v, yv.y);
            v = pk2(x1.w, x1.w); FMA2(acc[7][0], v, yv.x); FMA2(acc[7][1], v, yv.y);
        }
        __syncthreads();
    }

    float bb[4];
    #pragma unroll
    for (int j = 0; j < 4; j++) bb[j] = bias[n0 + tc * 4 + j];
    #pragma unroll
    for (int i = 0; i < 8; i++) {
        int row = m0 + tr * 4 + (i & 3) + (i >> 2) * 64;
        float2 p0 = upk2(acc[i][0]);
        float2 p1 = upk2(acc[i][1]);
        float4 o;
        o.x = p0.x + bb[0]; o.y = p0.y + bb[1];
        o.z = p1.x + bb[2]; o.w = p1.y + bb[3];
        if (act == 1) {
            o.x = fmaxf(o.x, 0.f); o.y = fmaxf(o.y, 0.f);
            o.z = fmaxf(o.z, 0.f); o.w = fmaxf(o.w, 0.f);
        }
        *(float4*)(C + (size_t)row * ldc + n0 + tc * 4) = o;
    }
}

// ---------------- embedding ----------------
__global__ void k_embed(const int* __restrict__ cls, const float* __restrict__ table,
                        float* __restrict__ feat) {
    int idx = blockIdx.x * 256 + threadIdx.x;
    if (idx >= NB * 16) return;
    int i = idx >> 4, j = idx & 15;
    int id = g_isI32 ? cls[i] : cls[2 * i];
    feat[i * FEAT + 128 + j] = table[id * 16 + j];
}

// ---------------- GRU ----------------
__global__ void k_gru(const float* __restrict__ gi, const float* __restrict__ gh,
                      const float* __restrict__ h, float* __restrict__ nh) {
    int idx = blockIdx.x * 256 + threadIdx.x;
    if (idx >= NB * HD) return;
    int i = idx >> 7, j = idx & 127;
    const float* a = gi + i * G3H;
    const float* c = gh + i * G3H;
    float r = 1.f / (1.f + __expf(-(a[j] + c[j])));
    float z = 1.f / (1.f + __expf(-(a[128 + j] + c[128 + j])));
    float n = tanhf(a[256 + j] + r * c[256 + j]);
    nh[idx] = (1.f - z) * n + z * h[idx];
}

// ---------------- fp32 -> bf16 convert (K and V fused) ----------------
__global__ void k_cvtbf2(const float* __restrict__ X1, __nv_bfloat16* __restrict__ Y1,
                         const float* __restrict__ X2, __nv_bfloat16* __restrict__ Y2) {
    int i = blockIdx.x * 256 + threadIdx.x;   // pairs
    float2 a = ((const float2*)X1)[i];
    float2 b = ((const float2*)X2)[i];
    ((__nv_bfloat162*)Y1)[i] = __floats2bfloat162_rn(a.x, a.y);
    ((__nv_bfloat162*)Y2)[i] = __floats2bfloat162_rn(b.x, b.y);
}

// ============ mma.sync bf16 flash attention (split-KV over 2 halves) ============
__global__ void __launch_bounds__(256, 1)
k_attn_mma(const float* __restrict__ Qf, const __nv_bfloat16* __restrict__ Kb,
           const __nv_bfloat16* __restrict__ Vb, const int* __restrict__ adj,
           float* __restrict__ Opart, float* __restrict__ lpart) {
    extern __shared__ char smem[];
    char* Ks = smem;            // 128 rows x 256B (swizzled)
    char* Vs = smem + 32768;
    uint32_t KsA = smem_u32(Ks);
    uint32_t VsA = smem_u32(Vs);

    int tid  = threadIdx.x;
    int wid  = tid >> 5;
    int lane = tid & 31;
    int m    = lane >> 3;
    int row0 = (blockIdx.x & 63) * 128;
    int half = blockIdx.x >> 6;
    int cst  = half * 4096;
    const float scale = 0.08838834764831845f;

    #pragma unroll
    for (int it = 0; it < 8; it++) {
        int id = tid + it * 256;
        int r = id >> 4, u = id & 15;
        const float4* qp = (const float4*)(Qf + (size_t)(row0 + r) * 128 + u * 8);
        float4 v0 = qp[0], v1 = qp[1];
        uint32_t pk[4] = { packbf(v0.x, v0.y), packbf(v0.z, v0.w),
                           packbf(v1.x, v1.y), packbf(v1.z, v1.w) };
        *(int4*)(Ks + r * 256 + ((u ^ (r & 7)) * 16)) = *(int4*)pk;
    }
    __syncthreads();

    uint32_t qf[8][4];
    #pragma unroll
    for (int kk = 0; kk < 8; kk++) {
        int r = wid * 16 + (m & 1) * 8 + (lane & 7);
        int u = kk * 2 + (m >> 1);
        uint32_t a = KsA + r * 256 + ((u ^ (r & 7)) * 16);
        LDSM_X4(qf[kk][0], qf[kk][1], qf[kk][2], qf[kk][3], a);
    }
    __syncthreads();

    float oacc[16][4];
    #pragma unroll
    for (int j = 0; j < 16; j++)
        #pragma unroll
        for (int i = 0; i < 4; i++) oacc[j][i] = 0.f;
    float lsum0 = 0.f, lsum1 = 0.f;

    int grow0 = row0 + wid * 16 + (lane >> 2);
    const int* adjr0 = adj + (size_t)grow0 * NB;
    const int* adjr1 = adjr0 + (size_t)8 * NB;

    for (int t = 0; t < 32; t++) {
        int c0 = cst + t * 128;
        #pragma unroll
        for (int it = 0; it < 8; it++) {
            int id = tid + it * 256;
            int r = id >> 4, u = id & 15;
            int4 kv = *(const int4*)(Kb + (size_t)(c0 + r) * 128 + u * 8);
            int4 vv = *(const int4*)(Vb + (size_t)(c0 + r) * 128 + u * 8);
            int off = r * 256 + ((u ^ (r & 7)) * 16);
            *(int4*)(Ks + off) = kv;
            *(int4*)(Vs + off) = vv;
        }
        __syncthreads();

        float sacc[16][4];
        #pragma unroll
        for (int j = 0; j < 16; j++)
            #pragma unroll
            for (int i = 0; i < 4; i++) sacc[j][i] = 0.f;

        #pragma unroll
        for (int kk = 0; kk < 8; kk++) {
            #pragma unroll
            for (int jp = 0; jp < 8; jp++) {
                int nr = jp * 16 + (m >> 1) * 8 + (lane & 7);
                int u  = kk * 2 + (m & 1);
                uint32_t a = KsA + nr * 256 + ((u ^ (nr & 7)) * 16);
                uint32_t b0, b1, b2, b3;
                LDSM_X4(b0, b1, b2, b3, a);
                MMA_BF16(sacc[2 * jp],     qf[kk], b0, b1);
                MMA_BF16(sacc[2 * jp + 1], qf[kk], b2, b3);
            }
        }

        uint32_t pf[8][4];
        int cb = c0 + (lane & 3) * 2;
        #pragma unroll
        for (int s = 0; s < 8; s++) {
            int ca = cb + s * 16;
            int cbb = ca + 8;
            int2 m00 = *(const int2*)(adjr0 + ca);
            int2 m01 = *(const int2*)(adjr1 + ca);
            int2 m10 = *(const int2*)(adjr0 + cbb);
            int2 m11 = *(const int2*)(adjr1 + cbb);
            float p00 = m00.x ? __expf(sacc[2 * s][0] * scale) : 0.f;
            float p01 = m00.y ? __expf(sacc[2 * s][1] * scale) : 0.f;
            float p02 = m01.x ? __expf(sacc[2 * s][2] * scale) : 0.f;
            float p03 = m01.y ? __expf(sacc[2 * s][3] * scale) : 0.f;
            float p10 = m10.x ? __expf(sacc[2 * s + 1][0] * scale) : 0.f;
            float p11 = m10.y ? __expf(sacc[2 * s + 1][1] * scale) : 0.f;
            float p12 = m11.x ? __expf(sacc[2 * s + 1][2] * scale) : 0.f;
            float p13 = m11.y ? __expf(sacc[2 * s + 1][3] * scale) : 0.f;
            lsum0 += (p00 + p01) + (p10 + p11);
            lsum1 += (p02 + p03) + (p12 + p13);
            pf[s][0] = packbf(p00, p01);
            pf[s][1] = packbf(p02, p03);
            pf[s][2] = packbf(p10, p11);
            pf[s][3] = packbf(p12, p13);
        }

        #pragma unroll
        for (int sp = 0; sp < 4; sp++) {
            #pragma unroll
            for (int jj = 0; jj < 16; jj++) {
                int cr = sp * 32 + m * 8 + (lane & 7);
                uint32_t a = VsA + cr * 256 + ((jj ^ (cr & 7)) * 16);
                uint32_t b0, b1, b2, b3;
                LDSM_X4T(b0, b1, b2, b3, a);
                MMA_BF16(oacc[jj], pf[2 * sp],     b0, b1);
                MMA_BF16(oacc[jj], pf[2 * sp + 1], b2, b3);
            }
        }
        __syncthreads();
    }

    lsum0 += __shfl_xor_sync(0xffffffffu, lsum0, 1);
    lsum0 += __shfl_xor_sync(0xffffffffu, lsum0, 2);
    lsum1 += __shfl_xor_sync(0xffffffffu, lsum1, 1);
    lsum1 += __shfl_xor_sync(0xffffffffu, lsum1, 2);
    if ((lane & 3) == 0) {
        lpart[half * NB + grow0]     = lsum0;
        lpart[half * NB + grow0 + 8] = lsum1;
    }
    float* o0 = Opart + ((size_t)half * NB + grow0) * 128 + (lane & 3) * 2;
    float* o1 = o0 + (size_t)8 * 128;
    #pragma unroll
    for (int jj = 0; jj < 16; jj++) {
        *(float2*)(o0 + jj * 8) = make_float2(oacc[jj][0], oacc[jj][1]);
        *(float2*)(o1 + jj * 8) = make_float2(oacc[jj][2], oacc[jj][3]);
    }
}

// ---------------- merge split-KV halves ----------------
__global__ void k_merge(const float* __restrict__ O, const float* __restrict__ l,
                        float* __restrict__ ctx) {
    int idx = blockIdx.x * 256 + threadIdx.x;
    int r = idx >> 7;
    float denom = l[r] + l[NB + r];
    ctx[idx] = (O[idx] + O[NB * HD + idx]) / denom;
}

// ---------------- final head ----------------
__global__ void k_fcq(const float* __restrict__ nh, const float* __restrict__ sw,
                      const float* __restrict__ W, const float* __restrict__ b,
                      float* __restrict__ q) {
    int idx = blockIdx.x * 256 + threadIdx.x;
    if (idx >= NB * 5) return;
    int i = idx / 5, a = idx % 5;
    const float* w = W + a * 256;
    const float* hr = nh + i * 128;
    const float* sr = sw + i * 128;
    float s = b[a];
    #pragma unroll 8
    for (int k = 0; k < 128; k++) s += hr[k] * w[k];
    #pragma unroll 8
    for (int k = 0; k < 128; k++) s += sr[k] * w[128 + k];
    q[idx] = s;
}

// ---------------- launch ----------------
extern "C" void kernel_launch(void* const* d_in, const int* in_sizes, int n_in,
                              void* d_out, int out_size) {
    const float* img = (const float*)d_in[0];
    const int*   adj = (const int*)  d_in[1];
    const int*   cls = (const int*)  d_in[2];
    const float* h0  = (const float*)d_in[3];
    const float* c1w = (const float*)d_in[4];
    const float* c1b = (const float*)d_in[5];
    const float* c2w = (const float*)d_in[6];
    const float* c2b = (const float*)d_in[7];
    const float* fvw = (const float*)d_in[8];
    const float* fvb = (const float*)d_in[9];
    const float* emb = (const float*)d_in[10];
    const float* wih = (const float*)d_in[11];
    const float* whh = (const float*)d_in[12];
    const float* bih = (const float*)d_in[13];
    const float* bhh = (const float*)d_in[14];
    const float* wqw = (const float*)d_in[15];
    const float* wqb = (const float*)d_in[16];
    const float* wkw = (const float*)d_in[17];
    const float* wkb = (const float*)d_in[18];
    const float* wvw = (const float*)d_in[19];
    const float* wvb = (const float*)d_in[20];
    const float* aow = (const float*)d_in[21];
    const float* aob = (const float*)d_in[22];
    const float* fqw = (const float*)d_in[23];
    const float* fqb = (const float*)d_in[24];

    float* qout = (float*)d_out;
    float* nh   = qout + NB * 5;

    float *pc1, *pflat, *pfeat, *pgi, *pgh, *pQ, *pK, *pV, *pctx, *pswarm, *pOp, *plp;
    __nv_bfloat16 *pKb, *pVb;
    cudaGetSymbolAddress((void**)&pc1,    g_conv1);
    cudaGetSymbolAddress((void**)&pflat,  g_flat);
    cudaGetSymbolAddress((void**)&pfeat,  g_feat);
    cudaGetSymbolAddress((void**)&pgi,    g_gi);
    cudaGetSymbolAddress((void**)&pgh,    g_gh);
    cudaGetSymbolAddress((void**)&pQ,     g_Q);
    cudaGetSymbolAddress((void**)&pK,     g_K);
    cudaGetSymbolAddress((void**)&pV,     g_V);
    cudaGetSymbolAddress((void**)&pctx,   g_ctx);
    cudaGetSymbolAddress((void**)&pswarm, g_swarm);
    cudaGetSymbolAddress((void**)&pKb,    g_Kb);
    cudaGetSymbolAddress((void**)&pVb,    g_Vb);
    cudaGetSymbolAddress((void**)&pOp,    g_Opart);
    cudaGetSymbolAddress((void**)&plp,    g_lpart);

    k_flag_init<<<1, 1>>>();
    k_flag_detect<<<16, 256>>>(cls);

    // CNN encoder (NCHW, f32x2)
    k_conv1<<<(NB * H1 * 6) / 256, 256>>>(img, c1w, c1b, pc1);    // 3456 blocks, 3px/thread
    k_conv2<<<NB / 8, 256>>>(pc1, c2w, c2b, pflat);               // 1024 blocks, warp-per-image

    // vis_feat = relu(flat @ fc_vis_w^T + b) into g_feat[:, :128]
    { dim3 g(128 / 64, NB / 128); k_gemm128<<<g, 256>>>(pflat, FLAT, fvw, FLAT, fvb, pfeat, FEAT, FLAT, 1); }
    k_embed<<<(NB * 16) / 256, 256>>>(cls, emb, pfeat);

    // GRU
    { dim3 g(G3H / 64, NB / 128); k_gemm128<<<g, 256>>>(pfeat, FEAT, wih, FEAT, bih, pgi, G3H, FEAT, 0); }
    { dim3 g(G3H / 64, NB / 128); k_gemm128<<<g, 256>>>(h0,    HD,   whh, HD,   bhh, pgh, G3H, HD,   0); }
    k_gru<<<(NB * HD) / 256, 256>>>(pgi, pgh, h0, nh);

    // Q, K, V projections (fp32)
    { dim3 g(HD / 64, NB / 128); k_gemm128<<<g, 256>>>(nh, HD, wqw, HD, wqb, pQ, HD, HD, 0); }
    { dim3 g(HD / 64, NB / 128); k_gemm128<<<g, 256>>>(nh, HD, wkw, HD, wkb, pK, HD, HD, 0); }
    { dim3 g(HD / 64, NB / 128); k_gemm128<<<g, 256>>>(nh, HD, wvw, HD, wvb, pV, HD, HD, 0); }

    // bf16 prep (fused K+V)
    k_cvtbf2<<<(NB * HD / 2) / 256, 256>>>(pK, pKb, pV, pVb);

    // mma.sync flash attention
    const int attn_smem = 65536;
    cudaFuncSetAttribute(k_attn_mma, cudaFuncAttributeMaxDynamicSharedMemorySize, attn_smem);
    k_attn_mma<<<128, 256, attn_smem>>>(pQ, pKb, pVb, adj, pOp, plp);
    k_merge<<<(NB * HD) / 256, 256>>>(pOp, plp, pctx);

    // attention output projection
    { dim3 g(HD / 64, NB / 128); k_gemm128<<<g, 256>>>(pctx, HD, aow, HD, aob, pswarm, HD, HD, 0); }

    k_fcq<<<(NB * 5 + 255) / 256, 256>>>(nh, pswarm, fqw, fqb, qout);
}